// round 7
// baseline (speedup 1.0000x reference)
#include <cuda_runtime.h>
#include <cuda_fp16.h>
#include <math.h>
#include <stdint.h>

#define TT 2048
#define NN 64
#define EE 1024
#define AA 256

// ---------------- device scratch (allocation-free rule) ----------------
__device__ float g_dproj[NN * AA];        // [n][a]
__device__ float g_scores[TT * NN];       // [t][n]
// W_e split fp16 hi/lo, PRE-SWIZZLED per (64-k chunk, 128-a half):
// byte index = chunk*32768 + half*16384 + SWZ((row%128)*128 + (k%64)*2)
__device__ unsigned char g_Wh[AA * EE * 2];
__device__ unsigned char g_Wl[AA * EE * 2];

#define SWZ(o) ((o) ^ ((((o) >> 3) & 0x70)))

// ---------------- PTX helpers (plain sm_100-legal) ----------------
__device__ __forceinline__ uint32_t smem_u32(const void* p) {
    uint32_t a;
    asm("{ .reg .u64 t; cvta.to.shared.u64 t, %1; cvt.u32.u64 %0, t; }"
        : "=r"(a) : "l"(p));
    return a;
}
__device__ __forceinline__ void cp16(uint32_t dst, const void* src) {
    asm volatile("cp.async.cg.shared.global [%0], [%1], 16;"
                 :: "r"(dst), "l"(src) : "memory");
}
__device__ __forceinline__ void cp_commit() {
    asm volatile("cp.async.commit_group;" ::: "memory");
}
__device__ __forceinline__ void cp_wait0() {
    asm volatile("cp.async.wait_group 0;" ::: "memory");
}
__device__ __forceinline__ void ldmx4(uint32_t addr, uint32_t& r0, uint32_t& r1,
                                      uint32_t& r2, uint32_t& r3) {
    asm volatile("ldmatrix.sync.aligned.m8n8.x4.shared.b16 {%0,%1,%2,%3}, [%4];"
                 : "=r"(r0), "=r"(r1), "=r"(r2), "=r"(r3) : "r"(addr));
}
__device__ __forceinline__ void sts128(uint32_t addr, uint32_t a, uint32_t b,
                                       uint32_t c, uint32_t d) {
    asm volatile("st.shared.v4.b32 [%0], {%1,%2,%3,%4};"
                 :: "r"(addr), "r"(a), "r"(b), "r"(c), "r"(d) : "memory");
}
__device__ __forceinline__ void mma16816(float* c, const uint32_t* a,
                                         uint32_t b0, uint32_t b1) {
    asm volatile("mma.sync.aligned.m16n8k16.row.col.f32.f16.f16.f32 "
                 "{%0,%1,%2,%3}, {%4,%5,%6,%7}, {%8,%9}, {%0,%1,%2,%3};"
                 : "+f"(c[0]), "+f"(c[1]), "+f"(c[2]), "+f"(c[3])
                 : "r"(a[0]), "r"(a[1]), "r"(a[2]), "r"(a[3]), "r"(b0), "r"(b1));
}
__device__ __forceinline__ float tanh_fast(float x) {
    float y;
    asm("tanh.approx.f32 %0, %1;" : "=f"(y) : "f"(x));
    return y;
}

// ---------------------------------------------------------------------------
// Kernel 0: split W_e into fp16 hi/lo, pre-swizzled per (chunk, a-half).
// ---------------------------------------------------------------------------
__global__ void wsplit_kernel(const float* __restrict__ W_e) {
    int row = blockIdx.x;
    int k4 = threadIdx.x * 4;
    float4 w = *(const float4*)(W_e + (size_t)row * EE + k4);
    int c = k4 >> 6, kl = k4 & 63;
    uint32_t off = (uint32_t)c * 32768u + (uint32_t)(row >> 7) * 16384u +
                   SWZ((uint32_t)((row & 127) * 128 + kl * 2));

    __half h0 = __float2half_rn(w.x), h1 = __float2half_rn(w.y);
    __half h2 = __float2half_rn(w.z), h3 = __float2half_rn(w.w);
    __half l0 = __float2half_rn(w.x - __half2float(h0));
    __half l1 = __float2half_rn(w.y - __half2float(h1));
    __half l2 = __float2half_rn(w.z - __half2float(h2));
    __half l3 = __float2half_rn(w.w - __half2float(h3));
    __half2 hA = __halves2half2(h0, h1), hB = __halves2half2(h2, h3);
    __half2 lA = __halves2half2(l0, l1), lB = __halves2half2(l2, l3);

    *(uint32_t*)(g_Wh + off)     = *(uint32_t*)&hA;
    *(uint32_t*)(g_Wh + off + 4) = *(uint32_t*)&hB;
    *(uint32_t*)(g_Wl + off)     = *(uint32_t*)&lA;
    *(uint32_t*)(g_Wl + off + 4) = *(uint32_t*)&lB;
}

// ---------------------------------------------------------------------------
// Kernel 1: d_proj[n][a] = sum_k dec_h[n][k] * W_d[a][k]
// ---------------------------------------------------------------------------
__global__ void dproj_kernel(const float* __restrict__ dec_h,
                             const float* __restrict__ W_d) {
    __shared__ float dh[EE];
    int n = blockIdx.x;
    for (int k = threadIdx.x; k < EE; k += blockDim.x) dh[k] = dec_h[n * EE + k];
    __syncthreads();
    int warp = threadIdx.x >> 5, lane = threadIdx.x & 31;
    const float4* dh4 = (const float4*)dh;
    for (int a = warp; a < AA; a += 8) {
        const float4* w4 = (const float4*)(W_d + (size_t)a * EE);
        float acc = 0.f;
        #pragma unroll 4
        for (int k = lane; k < EE / 4; k += 32) {
            float4 w = w4[k], d = dh4[k];
            acc += w.x * d.x + w.y * d.y + w.z * d.z + w.w * d.w;
        }
        #pragma unroll
        for (int off = 16; off; off >>= 1)
            acc += __shfl_xor_sync(0xffffffffu, acc, off);
        if (lane == 0) g_dproj[n * AA + a] = acc;
    }
}

// ---------------------------------------------------------------------------
// Kernel 1b: zero the score accumulator (scores built via atomicAdd halves).
// ---------------------------------------------------------------------------
__global__ void zero_scores_kernel() {
    g_scores[blockIdx.x * 256 + threadIdx.x] = 0.f;
}

// ---------------------------------------------------------------------------
// Kernel 2: fused score via mma.sync, 2-pass W split, 2 CTAs/SM.
//   CTA tile: BM=64 (one t), BN=128 (one a-half), BK=64. 256 thr, 8 warps
//   (2m x 4n), warp tile 32x32. Partial scores -> atomicAdd into g_scores
//   (exactly 2 addends per address -> commutative -> deterministic).
// ---------------------------------------------------------------------------
#define XS_OFF(b)    ((b) * 8192)
#define WS_OFF(b, s) (16384 + (b) * 32768 + (s) * 16384)
#define SCORE_SMEM   81920
#define DPS 132

extern "C" __global__ void __launch_bounds__(256, 2)
score_kernel(const float* __restrict__ enc, const float* __restrict__ v) {
    extern __shared__ char dsm[];
    __shared__ float red[64][4];
    __shared__ __align__(16) float sv[128];

    const int tid = threadIdx.x;
    const int lane = tid & 31, wid = tid >> 5;
    const int wm = wid & 1, wn = wid >> 1;
    const int t = blockIdx.x >> 1, h = blockIdx.x & 1;
    const uint32_t smem = smem_u32(dsm);

    // ---- X mapping: row = tid>>2 (n), quarter = tid&3 (16 k each) ----
    const int xrow = tid >> 2, xq = tid & 3;
    const float* xg = enc + ((size_t)t * 64 + xrow) * EE + xq * 16;
    const uint32_t xsts0 = SWZ((uint32_t)(xrow * 128 + xq * 32));
    const uint32_t xsts1 = SWZ((uint32_t)(xrow * 128 + xq * 32 + 16));

    // ---- ldmatrix per-thread geometry ----
    const int g = lane >> 3, lr8 = lane & 7;
    const int arow = wm * 32 + lr8 + (g & 1) * 8;   // + mi*16
    const int brow = wn * 32 + lr8 + (g & 1) * 8;   // + nb*16
    const int kgrp = (g >> 1) * 16;                 // + ks*32 (bytes)

    const unsigned char* wsrc_h = g_Wh + h * 16384;
    const unsigned char* wsrc_l = g_Wl + h * 16384;

    float acc[2][4][4];
    #pragma unroll
    for (int mi = 0; mi < 2; mi++)
        #pragma unroll
        for (int nt = 0; nt < 4; nt++)
            #pragma unroll
            for (int q = 0; q < 4; q++) acc[mi][nt][q] = 0.f;

    // ---- prologue: chunk 0 ----
    float4 pa[4];
    {
        const float4* p = (const float4*)xg;
        #pragma unroll
        for (int u = 0; u < 4; u++) pa[u] = __ldg(p + u);
        __half2 q0 = __floats2half2_rn(pa[0].x, pa[0].y);
        __half2 q1 = __floats2half2_rn(pa[0].z, pa[0].w);
        __half2 q2 = __floats2half2_rn(pa[1].x, pa[1].y);
        __half2 q3 = __floats2half2_rn(pa[1].z, pa[1].w);
        sts128(smem + XS_OFF(0) + xsts0,
               *(uint32_t*)&q0, *(uint32_t*)&q1, *(uint32_t*)&q2, *(uint32_t*)&q3);
        q0 = __floats2half2_rn(pa[2].x, pa[2].y);
        q1 = __floats2half2_rn(pa[2].z, pa[2].w);
        q2 = __floats2half2_rn(pa[3].x, pa[3].y);
        q3 = __floats2half2_rn(pa[3].z, pa[3].w);
        sts128(smem + XS_OFF(0) + xsts1,
               *(uint32_t*)&q0, *(uint32_t*)&q1, *(uint32_t*)&q2, *(uint32_t*)&q3);
        #pragma unroll
        for (int s = 0; s < 2; s++) {
            const unsigned char* src = (s ? wsrc_l : wsrc_h) + tid * 16;
            uint32_t dst = smem + WS_OFF(0, s) + tid * 16;
            #pragma unroll
            for (int r = 0; r < 4; r++)
                cp16(dst + r * 4096, src + r * 4096);
        }
        cp_commit();
    }

    for (int c = 0; c < 16; c++) {
        const int b = c & 1;
        if (c < 15) {   // LDG next X early
            const float4* p = (const float4*)(xg + (c + 1) * 64);
            #pragma unroll
            for (int u = 0; u < 4; u++) pa[u] = __ldg(p + u);
        }
        cp_wait0();
        __syncthreads();   // XS[b], WS[b] ready; b^1 free

        if (c < 15) {
            __half2 q0 = __floats2half2_rn(pa[0].x, pa[0].y);
            __half2 q1 = __floats2half2_rn(pa[0].z, pa[0].w);
            __half2 q2 = __floats2half2_rn(pa[1].x, pa[1].y);
            __half2 q3 = __floats2half2_rn(pa[1].z, pa[1].w);
            sts128(smem + XS_OFF(b ^ 1) + xsts0,
                   *(uint32_t*)&q0, *(uint32_t*)&q1, *(uint32_t*)&q2, *(uint32_t*)&q3);
            q0 = __floats2half2_rn(pa[2].x, pa[2].y);
            q1 = __floats2half2_rn(pa[2].z, pa[2].w);
            q2 = __floats2half2_rn(pa[3].x, pa[3].y);
            q3 = __floats2half2_rn(pa[3].z, pa[3].w);
            sts128(smem + XS_OFF(b ^ 1) + xsts1,
                   *(uint32_t*)&q0, *(uint32_t*)&q1, *(uint32_t*)&q2, *(uint32_t*)&q3);
            #pragma unroll
            for (int s = 0; s < 2; s++) {
                const unsigned char* src =
                    (s ? wsrc_l : wsrc_h) + (size_t)(c + 1) * 32768 + tid * 16;
                uint32_t dst = smem + WS_OFF(b ^ 1, s) + tid * 16;
                #pragma unroll
                for (int r = 0; r < 4; r++)
                    cp16(dst + r * 4096, src + r * 4096);
            }
            cp_commit();
        }

        // ---- MMA on buffer b ----
        #pragma unroll
        for (int ks = 0; ks < 4; ks++) {
            uint32_t afr[2][4];
            #pragma unroll
            for (int mi = 0; mi < 2; mi++) {
                uint32_t ad = smem + XS_OFF(b) +
                              SWZ((uint32_t)((arow + mi * 16) * 128 + kgrp + ks * 32));
                ldmx4(ad, afr[mi][0], afr[mi][1], afr[mi][2], afr[mi][3]);
            }
            #pragma unroll
            for (int s = 0; s < 2; s++) {
                #pragma unroll
                for (int nb = 0; nb < 2; nb++) {
                    uint32_t bfr[4];
                    uint32_t bd = smem + WS_OFF(b, s) +
                                  SWZ((uint32_t)((brow + nb * 16) * 128 + kgrp + ks * 32));
                    ldmx4(bd, bfr[0], bfr[1], bfr[2], bfr[3]);
                    #pragma unroll
                    for (int mi = 0; mi < 2; mi++)
                        #pragma unroll
                        for (int j = 0; j < 2; j++)
                            mma16816(acc[mi][nb * 2 + j], afr[mi], bfr[j], bfr[2 + j]);
                }
            }
        }
    }

    // ---- epilogue: tanh(+dproj) * v, reduce over this CTA's 128 a ----
    __syncthreads();
    float* dps = (float*)dsm;           // 64 x 128 (stride DPS), reuses tile area
    for (int i = tid; i < 64 * 128; i += 256) {
        int n = i >> 7, al = i & 127;
        dps[n * DPS + al] = g_dproj[n * AA + h * 128 + al];
    }
    if (tid < 128) sv[tid] = v[h * 128 + tid];
    __syncthreads();

    #pragma unroll
    for (int mi = 0; mi < 2; mi++) {
        #pragma unroll
        for (int half = 0; half < 2; half++) {
            int r = wm * 32 + mi * 16 + (lane >> 2) + half * 8;   // n index
            float partial = 0.f;
            #pragma unroll
            for (int nt = 0; nt < 4; nt++) {
                int col = wn * 32 + nt * 8 + 2 * (lane & 3);
                float2 dp = *(const float2*)(dps + r * DPS + col);
                float2 vvv = *(const float2*)(sv + col);
                float x0 = acc[mi][nt][half * 2 + 0] + dp.x;
                float x1 = acc[mi][nt][half * 2 + 1] + dp.y;
                partial = fmaf(tanh_fast(x0), vvv.x, partial);
                partial = fmaf(tanh_fast(x1), vvv.y, partial);
            }
            partial += __shfl_xor_sync(0xffffffffu, partial, 1);
            partial += __shfl_xor_sync(0xffffffffu, partial, 2);
            if ((lane & 3) == 0) red[r][wn] = partial;
        }
    }
    __syncthreads();
    if (tid < 64) {
        float s = red[tid][0] + red[tid][1] + red[tid][2] + red[tid][3];
        atomicAdd(&g_scores[t * NN + tid], s);
    }
}

// ---------------------------------------------------------------------------
// Kernel 3: softmax over t per column n
// ---------------------------------------------------------------------------
__global__ void softmax_kernel(float* __restrict__ alpha) {
    int n = blockIdx.x, tid = threadIdx.x;
    int warp = tid >> 5, lane = tid & 31;
    __shared__ float red_max[8];
    __shared__ float red_sum[8];

    float vals[8];
    float lmax = -1e30f;
    #pragma unroll
    for (int i = 0; i < 8; i++) {
        vals[i] = g_scores[(i * 256 + tid) * NN + n];
        lmax = fmaxf(lmax, vals[i]);
    }
    #pragma unroll
    for (int off = 16; off; off >>= 1)
        lmax = fmaxf(lmax, __shfl_xor_sync(0xffffffffu, lmax, off));
    if (lane == 0) red_max[warp] = lmax;
    __syncthreads();
    float bmax = red_max[0];
    #pragma unroll
    for (int w = 1; w < 8; w++) bmax = fmaxf(bmax, red_max[w]);

    float lsum = 0.f;
    #pragma unroll
    for (int i = 0; i < 8; i++) {
        vals[i] = expf(vals[i] - bmax);
        lsum += vals[i];
    }
    #pragma unroll
    for (int off = 16; off; off >>= 1)
        lsum += __shfl_xor_sync(0xffffffffu, lsum, off);
    if (lane == 0) red_sum[warp] = lsum;
    __syncthreads();
    float bsum = 0.f;
    #pragma unroll
    for (int w = 0; w < 8; w++) bsum += red_sum[w];
    float inv = 1.f / bsum;

    #pragma unroll
    for (int i = 0; i < 8; i++)
        alpha[(i * 256 + tid) * NN + n] = vals[i] * inv;
}

// ---------------------------------------------------------------------------
__global__ void zero_ctx_kernel(float* __restrict__ ctx) {
    ctx[blockIdx.x * 256 + threadIdx.x] = 0.f;
}

__global__ void ctx_kernel(const float* __restrict__ enc,
                           const float* __restrict__ alpha,
                           float* __restrict__ ctx) {
    int n = blockIdx.y;
    int echunk = blockIdx.x & 7;
    int tchunk = blockIdx.x >> 3;
    int e = echunk * 128 + threadIdx.x;
    int t0 = tchunk * 512;

    const float* base = enc + (size_t)n * EE + e;
    float acc = 0.f;
    #pragma unroll 4
    for (int t = t0; t < t0 + 512; t++) {
        float a = alpha[t * NN + n];
        acc += a * base[(size_t)t * NN * EE];
    }
    atomicAdd(&ctx[n * EE + e], acc);
}

// ---------------------------------------------------------------------------
extern "C" void kernel_launch(void* const* d_in, const int* in_sizes, int n_in,
                              void* d_out, int out_size) {
    const float* enc_out = (const float*)d_in[0];  // [2048, 64, 1024]
    const float* dec_h   = (const float*)d_in[1];  // [64, 1024]
    const float* W_e     = (const float*)d_in[2];  // [256, 1024]
    const float* W_d     = (const float*)d_in[3];  // [256, 1024]
    const float* v       = (const float*)d_in[4];  // [1, 256]

    float* out   = (float*)d_out;
    float* ctx   = out;                 // [64, 1024]
    float* alpha = out + NN * EE;       // [2048, 64]

    cudaFuncSetAttribute(score_kernel,
                         cudaFuncAttributeMaxDynamicSharedMemorySize, SCORE_SMEM);

    wsplit_kernel<<<AA, 256>>>(W_e);                        // launch 0
    dproj_kernel<<<NN, 256>>>(dec_h, W_d);                  // launch 1
    zero_scores_kernel<<<TT * NN / 256, 256>>>();           // launch 2 (ncu pad)
    score_kernel<<<TT * 2, 256, SCORE_SMEM>>>(enc_out, v);  // launch 3 <- profile
    softmax_kernel<<<NN, 256>>>(alpha);                     // launch 4
    zero_ctx_kernel<<<(NN * EE) / 256, 256>>>(ctx);         // launch 5
    ctx_kernel<<<dim3(32, NN), 128>>>(enc_out, alpha, ctx); // launch 6
}